// round 1
// baseline (speedup 1.0000x reference)
#include <cuda_runtime.h>

#define B 32
#define S 1024
#define W 512
#define D 768
#define NPOS 32

// One CTA per (b, w). 192 threads, one float4 each across D=768.
__global__ void __launch_bounds__(192, 8) charpool_kernel(
    const float* __restrict__ feats,      // [B, S, D]
    const int* __restrict__ word_lens,    // [B, W]
    const int* __restrict__ seq_len,      // [B]
    const int* __restrict__ pos,          // [B, W]
    const float* __restrict__ pos_table,  // [NPOS, D]
    float* __restrict__ out)              // [B, W, D]
{
    const int w = blockIdx.x;
    const int b = blockIdx.y;
    const int t = threadIdx.x;  // 0..191, one float4 column group

    const int start = word_lens[b * W + w];
    const int nxt   = (w + 1 < W) ? word_lens[b * W + w + 1] : 0;
    const int end   = (nxt == 0) ? seq_len[b] : nxt;
    const bool valid = (start != 0) || (w == 0);

    const int p = pos[b * W + w];
    const float4 pt = reinterpret_cast<const float4*>(pos_table + (size_t)p * D)[t];

    float4 r;
    if (valid) {
        float4 acc = make_float4(0.f, 0.f, 0.f, 0.f);
        const float4* fp = reinterpret_cast<const float4*>(
            feats + ((size_t)b * S + (size_t)start) * D) + t;
        const int len = end - start;
        #pragma unroll 2
        for (int s = 0; s < len; ++s) {
            float4 v = *fp;
            acc.x += v.x; acc.y += v.y; acc.z += v.z; acc.w += v.w;
            fp += D / 4;
        }
        const float inv = 1.0f / (float)(len > 0 ? len : 1);
        r.x = acc.x * inv + pt.x;
        r.y = acc.y * inv + pt.y;
        r.z = acc.z * inv + pt.z;
        r.w = acc.w * inv + pt.w;
    } else {
        r = pt;  // pos=0 row is zeroed in the table -> zeros out
    }

    reinterpret_cast<float4*>(out + ((size_t)b * W + (size_t)w) * D)[t] = r;
}

extern "C" void kernel_launch(void* const* d_in, const int* in_sizes, int n_in,
                              void* d_out, int out_size)
{
    const float* feats     = (const float*)d_in[0];
    const int*   word_lens = (const int*)d_in[1];
    const int*   seq_len   = (const int*)d_in[2];
    const int*   pos       = (const int*)d_in[3];
    const float* pos_table = (const float*)d_in[4];
    float* out = (float*)d_out;

    dim3 grid(W, B);
    charpool_kernel<<<grid, 192>>>(feats, word_lens, seq_len, pos, pos_table, out);
}